// round 14
// baseline (speedup 1.0000x reference)
#include <cuda_runtime.h>
#include <cuda_bf16.h>
#include <cstdint>
#include <cstddef>

#define NN 50000
#define NE 800000
#define SCAN_CH 196          // ceil(50000/256)
#define SCAN_B  256

// ---------------- scratch (static __device__ arrays; no allocs allowed) ------
__device__ __align__(16) __nv_bfloat16 g_bufA[(size_t)NN * 256];  // 25.6 MB
__device__ __align__(16) __nv_bfloat16 g_bufB[(size_t)NN * 512];  // 51.2 MB
// pre-split weights: packed bf16x2 (k,k+1) hi/lo, layout [K/2][N] uints
__device__ __align__(16) unsigned g_wh1[64 * 256],  g_wl1[64 * 256];
__device__ __align__(16) unsigned g_wh2[128 * 512], g_wl2[128 * 512];
__device__ __align__(16) unsigned g_wh3[256 * 256], g_wl3[256 * 256];
__device__ float g_dinv[NN];
__device__ int   g_deg[NN];
__device__ int   g_off[NN];
__device__ int   g_cur[NN];
__device__ int   g_src[NE];
__device__ int   g_bsum[SCAN_B];
__device__ int   g_boff[SCAN_B];
__device__ float g_gsum[256];

// ---------------- setup kernels ---------------------------------------------
__global__ void init_kernel() {
    int i = blockIdx.x * blockDim.x + threadIdx.x;
    if (i < NN) { g_deg[i] = 0; g_cur[i] = 0; }
    if (i < 256) g_gsum[i] = 0.f;
}

__global__ void count_kernel(const int* __restrict__ col, int E) {
    int e = blockIdx.x * blockDim.x + threadIdx.x;
    if (e < E) atomicAdd(&g_deg[col[e]], 1);
}

__global__ void dinv_kernel(int n) {
    int i = blockIdx.x * blockDim.x + threadIdx.x;
    if (i < n) g_dinv[i] = rsqrtf((float)(g_deg[i] + 1));
}

__device__ __forceinline__ unsigned pack_bf2(float a, float b) {
    __nv_bfloat162 h = __floats2bfloat162_rn(a, b);
    return *(unsigned*)&h;
}

// split W[K,N] fp32 into packed hi/lo kpair uints [K/2][N]
__global__ void split_w_kernel(const float* __restrict__ W,
                               unsigned* __restrict__ Wh, unsigned* __restrict__ Wl,
                               int K2, int N) {
    int idx = blockIdx.x * blockDim.x + threadIdx.x;
    if (idx >= K2 * N) return;
    int kp = idx / N, c = idx - kp * N;
    float f0 = W[(size_t)(2 * kp) * N + c];
    float f1 = W[(size_t)(2 * kp + 1) * N + c];
    float h0 = __bfloat162float(__float2bfloat16(f0));
    float h1 = __bfloat162float(__float2bfloat16(f1));
    Wh[idx] = pack_bf2(h0, h1);
    Wl[idx] = pack_bf2(f0 - h0, f1 - h1);
}

// --- hierarchical exclusive scan of g_deg -> g_off ---------------------------
__global__ void scanA_kernel(int n) {
    __shared__ int ws[8];
    int t = threadIdx.x, lane = t & 31, wid = t >> 5;
    int i = blockIdx.x * SCAN_CH + t;
    int v = (t < SCAN_CH && i < n) ? g_deg[i] : 0;
    #pragma unroll
    for (int d = 16; d > 0; d >>= 1) v += __shfl_down_sync(0xffffffffu, v, d);
    if (lane == 0) ws[wid] = v;
    __syncthreads();
    if (t == 0) {
        int s = 0;
        #pragma unroll
        for (int w = 0; w < 8; w++) s += ws[w];
        g_bsum[blockIdx.x] = s;
    }
}

__global__ void scanB_kernel() {
    __shared__ int ws[8];
    int t = threadIdx.x, lane = t & 31, wid = t >> 5;
    int s = g_bsum[t];
    int v = s;
    #pragma unroll
    for (int d = 1; d < 32; d <<= 1) {
        int u = __shfl_up_sync(0xffffffffu, v, d);
        if (lane >= d) v += u;
    }
    if (lane == 31) ws[wid] = v;
    __syncthreads();
    if (wid == 0 && lane < 8) {
        int w = ws[lane];
        #pragma unroll
        for (int d = 1; d < 8; d <<= 1) {
            int u = __shfl_up_sync(0xffu, w, d);
            if (lane >= d) w += u;
        }
        ws[lane] = w;
    }
    __syncthreads();
    g_boff[t] = (v - s) + (wid ? ws[wid - 1] : 0);
}

__global__ void scanC_kernel(int n) {
    __shared__ int ws[8];
    int t = threadIdx.x, lane = t & 31, wid = t >> 5;
    int i = blockIdx.x * SCAN_CH + t;
    int s = (t < SCAN_CH && i < n) ? g_deg[i] : 0;
    int v = s;
    #pragma unroll
    for (int d = 1; d < 32; d <<= 1) {
        int u = __shfl_up_sync(0xffffffffu, v, d);
        if (lane >= d) v += u;
    }
    if (lane == 31) ws[wid] = v;
    __syncthreads();
    if (wid == 0 && lane < 8) {
        int w = ws[lane];
        #pragma unroll
        for (int d = 1; d < 8; d <<= 1) {
            int u = __shfl_up_sync(0xffu, w, d);
            if (lane >= d) w += u;
        }
        ws[lane] = w;
    }
    __syncthreads();
    if (t < SCAN_CH && i < n)
        g_off[i] = g_boff[blockIdx.x] + (v - s) + (wid ? ws[wid - 1] : 0);
}

__global__ void scatter_kernel(const int* __restrict__ row,
                               const int* __restrict__ col, int E) {
    int e = blockIdx.x * blockDim.x + threadIdx.x;
    if (e >= E) return;
    int c = col[e];
    int p = g_off[c] + atomicAdd(&g_cur[c], 1);
    g_src[p] = row[e];
}

// ---------------- propagation kernels (R4-proven) -----------------------------
__global__ void prop_f32_kernel(const float* __restrict__ in,
                                __nv_bfloat16* __restrict__ out, int n) {
    int warp = (blockIdx.x * blockDim.x + threadIdx.x) >> 5;
    int lane = threadIdx.x & 31;
    if (warp >= n) return;
    float dn = g_dinv[warp];
    float ws = dn * dn;
    float4 t = __ldg((const float4*)(in + (size_t)warp * 128 + lane * 4));
    float4 acc = make_float4(t.x * ws, t.y * ws, t.z * ws, t.w * ws);
    int s = g_off[warp];
    int e = s + g_deg[warp];
    for (int j = s; j < e; j++) {
        int r = __ldg(&g_src[j]);
        float wr = __ldg(&g_dinv[r]) * dn;
        float4 u = __ldg((const float4*)(in + (size_t)r * 128 + lane * 4));
        acc.x += u.x * wr; acc.y += u.y * wr; acc.z += u.z * wr; acc.w += u.w * wr;
    }
    __nv_bfloat162 o0 = __floats2bfloat162_rn(acc.x, acc.y);
    __nv_bfloat162 o1 = __floats2bfloat162_rn(acc.z, acc.w);
    uint2 o; o.x = *(unsigned*)&o0; o.y = *(unsigned*)&o1;
    *(uint2*)(out + (size_t)warp * 128 + lane * 4) = o;
}

__global__ void prop_bf16_kernel(const __nv_bfloat16* __restrict__ in,
                                 __nv_bfloat16* __restrict__ out, int n) {
    int warp = (blockIdx.x * blockDim.x + threadIdx.x) >> 5;
    int lane = threadIdx.x & 31;
    if (warp >= n) return;
    float dn = g_dinv[warp];
    float ws = dn * dn;
    float acc[8];
    {
        uint4 u = __ldg((const uint4*)(in + (size_t)warp * 256 + lane * 8));
        float2 f0 = __bfloat1622float2(*(__nv_bfloat162*)&u.x);
        float2 f1 = __bfloat1622float2(*(__nv_bfloat162*)&u.y);
        float2 f2 = __bfloat1622float2(*(__nv_bfloat162*)&u.z);
        float2 f3 = __bfloat1622float2(*(__nv_bfloat162*)&u.w);
        acc[0] = f0.x * ws; acc[1] = f0.y * ws; acc[2] = f1.x * ws; acc[3] = f1.y * ws;
        acc[4] = f2.x * ws; acc[5] = f2.y * ws; acc[6] = f3.x * ws; acc[7] = f3.y * ws;
    }
    int s = g_off[warp];
    int e = s + g_deg[warp];
    for (int j = s; j < e; j++) {
        int r = __ldg(&g_src[j]);
        float wr = __ldg(&g_dinv[r]) * dn;
        uint4 u = __ldg((const uint4*)(in + (size_t)r * 256 + lane * 8));
        float2 f0 = __bfloat1622float2(*(__nv_bfloat162*)&u.x);
        float2 f1 = __bfloat1622float2(*(__nv_bfloat162*)&u.y);
        float2 f2 = __bfloat1622float2(*(__nv_bfloat162*)&u.z);
        float2 f3 = __bfloat1622float2(*(__nv_bfloat162*)&u.w);
        acc[0] += f0.x * wr; acc[1] += f0.y * wr; acc[2] += f1.x * wr; acc[3] += f1.y * wr;
        acc[4] += f2.x * wr; acc[5] += f2.y * wr; acc[6] += f3.x * wr; acc[7] += f3.y * wr;
    }
    __nv_bfloat162 o0 = __floats2bfloat162_rn(acc[0], acc[1]);
    __nv_bfloat162 o1 = __floats2bfloat162_rn(acc[2], acc[3]);
    __nv_bfloat162 o2 = __floats2bfloat162_rn(acc[4], acc[5]);
    __nv_bfloat162 o3 = __floats2bfloat162_rn(acc[6], acc[7]);
    uint4 o; o.x = *(unsigned*)&o0; o.y = *(unsigned*)&o1;
    o.z = *(unsigned*)&o2; o.w = *(unsigned*)&o3;
    *(uint4*)(out + (size_t)warp * 256 + lane * 8) = o;
}

// layer-3 prop + relu + bias + mean-pool fused; warp-per-node (full parallelism),
// per-block smem reduction -> one atomicAdd per dim per block.
__global__ void prop_pool_kernel(const __nv_bfloat16* __restrict__ in,
                                 const float* __restrict__ b3, int n) {
    __shared__ float red[8][256];
    int wid = threadIdx.x >> 5, lane = threadIdx.x & 31;
    int node = blockIdx.x * 8 + wid;
    float vals[8];
    if (node < n) {
        float dn = g_dinv[node];
        float ws = dn * dn;
        float acc[8];
        {
            uint4 u = __ldg((const uint4*)(in + (size_t)node * 256 + lane * 8));
            float2 f0 = __bfloat1622float2(*(__nv_bfloat162*)&u.x);
            float2 f1 = __bfloat1622float2(*(__nv_bfloat162*)&u.y);
            float2 f2 = __bfloat1622float2(*(__nv_bfloat162*)&u.z);
            float2 f3 = __bfloat1622float2(*(__nv_bfloat162*)&u.w);
            acc[0] = f0.x * ws; acc[1] = f0.y * ws; acc[2] = f1.x * ws; acc[3] = f1.y * ws;
            acc[4] = f2.x * ws; acc[5] = f2.y * ws; acc[6] = f3.x * ws; acc[7] = f3.y * ws;
        }
        int s = g_off[node];
        int e = s + g_deg[node];
        for (int j = s; j < e; j++) {
            int r = __ldg(&g_src[j]);
            float wr = __ldg(&g_dinv[r]) * dn;
            uint4 u = __ldg((const uint4*)(in + (size_t)r * 256 + lane * 8));
            float2 f0 = __bfloat1622float2(*(__nv_bfloat162*)&u.x);
            float2 f1 = __bfloat1622float2(*(__nv_bfloat162*)&u.y);
            float2 f2 = __bfloat1622float2(*(__nv_bfloat162*)&u.z);
            float2 f3 = __bfloat1622float2(*(__nv_bfloat162*)&u.w);
            acc[0] += f0.x * wr; acc[1] += f0.y * wr; acc[2] += f1.x * wr; acc[3] += f1.y * wr;
            acc[4] += f2.x * wr; acc[5] += f2.y * wr; acc[6] += f3.x * wr; acc[7] += f3.y * wr;
        }
        #pragma unroll
        for (int q = 0; q < 8; q++)
            vals[q] = fmaxf(acc[q] + b3[lane * 8 + q], 0.f);
    } else {
        #pragma unroll
        for (int q = 0; q < 8; q++) vals[q] = 0.f;
    }
    #pragma unroll
    for (int q = 0; q < 8; q++) red[wid][lane * 8 + q] = vals[q];
    __syncthreads();
    int t = threadIdx.x;
    float s = 0.f;
    #pragma unroll
    for (int w = 0; w < 8; w++) s += red[w][t];
    atomicAdd(&g_gsum[t], s);
}

// ---------------- split-precision bf16 GEMM, cp.async 3-stage ----------------
// C = [relu](A @ (Wh + Wl) + bias). A[M,K] bf16 rm; Wh/Wl [K/2][N] packed uints.
// CTA 128x128, warp 64x32, BK=32, mma m16n8k16 bf16, fp32 accum.
#define AS_STR 20    // uints/row (16 used)
#define BS_STR 136   // uints/kpair-row (128 used)
#define AS_TILE (128 * AS_STR)   // 2560 uints
#define BS_TILE (16 * BS_STR)    // 2176 uints
#define STAGE_U (AS_TILE + 2 * BS_TILE)         // 6912 uints per stage
#define GEMM_SMEM (3 * STAGE_U * 4)             // 82944 B

#define CP16(dst_u32, src) \
    asm volatile("cp.async.cg.shared.global [%0], [%1], 16;" :: "r"(dst_u32), "l"(src))

__global__ __launch_bounds__(256, 2)
void gemm_split(const __nv_bfloat16* __restrict__ A, const unsigned* __restrict__ Wh,
                const unsigned* __restrict__ Wl, const float* __restrict__ bias,
                __nv_bfloat16* __restrict__ C, int M, int N, int K, int relu) {
    extern __shared__ unsigned smem[];
    const unsigned sb = (unsigned)__cvta_generic_to_shared(smem);

    const int tid = threadIdx.x, lane = tid & 31, wid = tid >> 5;
    const int m0 = blockIdx.y * 128, n0 = blockIdx.x * 128;
    const int wm = (wid >> 2) * 64;
    const int wn = (wid & 3) * 32;

    // A loader: 512 chunks of 16B (row, 4-uint group), 2 per thread
    const int a_r0 = tid >> 2;             // 0..63
    const int a_r1 = a_r0 + 64;            // 64..127
    const int a_q = (tid & 3) * 4;         // uint offset 0,4,8,12
    const int a_rc0 = min(m0 + a_r0, M - 1);
    const int a_rc1 = min(m0 + a_r1, M - 1);
    // B loader: 512 chunks per array, 2 per thread
    const int b_kp0 = tid >> 5;            // 0..7
    const int b_kp1 = b_kp0 + 8;           // 8..15
    const int b_g = (tid & 31) * 4;        // col 0..124

    float acc[4][4][4];
    #pragma unroll
    for (int i = 0; i < 4; i++)
        #pragma unroll
        for (int j = 0; j < 4; j++)
            #pragma unroll
            for (int q = 0; q < 4; q++) acc[i][j][q] = 0.f;

    #define CPA_TILE(kt_, buf_) do {                                            \
        int k0_ = (kt_) << 5;                                                   \
        unsigned stage = sb + (buf_) * STAGE_U * 4;                             \
        unsigned adst = stage;                                                  \
        unsigned hdst = stage + AS_TILE * 4;                                    \
        unsigned ldst = stage + (AS_TILE + BS_TILE) * 4;                        \
        CP16(adst + (a_r0 * AS_STR + a_q) * 4,                                  \
             A + (size_t)a_rc0 * K + k0_ + a_q * 2);                            \
        CP16(adst + (a_r1 * AS_STR + a_q) * 4,                                  \
             A + (size_t)a_rc1 * K + k0_ + a_q * 2);                            \
        int kb_ = k0_ >> 1;                                                     \
        CP16(hdst + (b_kp0 * BS_STR + b_g) * 4,                                 \
             Wh + (size_t)(kb_ + b_kp0) * N + n0 + b_g);                        \
        CP16(hdst + (b_kp1 * BS_STR + b_g) * 4,                                 \
             Wh + (size_t)(kb_ + b_kp1) * N + n0 + b_g);                        \
        CP16(ldst + (b_kp0 * BS_STR + b_g) * 4,                                 \
             Wl + (size_t)(kb_ + b_kp0) * N + n0 + b_g);                        \
        CP16(ldst + (b_kp1 * BS_STR + b_g) * 4,                                 \
             Wl + (size_t)(kb_ + b_kp1) * N + n0 + b_g);                        \
        asm volatile("cp.async.commit_group;");                                 \
    } while (0)

    const int KT = K >> 5;
    CPA_TILE(0, 0);
    if (KT > 1) CPA_TILE(1, 1);
    for (int kt = 0; kt < KT; kt++) {
        const int cur = kt % 3;
        if (kt + 2 < KT) {
            CPA_TILE(kt + 2, (kt + 2) % 3);
            asm volatile("cp.async.wait_group 2;");
        } else if (kt + 1 < KT) {
            asm volatile("cp.async.wait_group 1;");
        } else {
            asm volatile("cp.async.wait_group 0;");
        }
        __syncthreads();

        const unsigned* St = smem + cur * STAGE_U;
        const unsigned* As_ = St;
        const unsigned* BH_ = St + AS_TILE;
        const unsigned* BL_ = St + AS_TILE + BS_TILE;
        #pragma unroll
        for (int ks = 0; ks < 2; ks++) {
            unsigned a[4][4], bh[4][2], bl[4][2];
            int kc = ks * 8 + (lane & 3);
            #pragma unroll
            for (int mt = 0; mt < 4; mt++) {
                int r = wm + mt * 16 + (lane >> 2);
                a[mt][0] = As_[r * AS_STR + kc];
                a[mt][1] = As_[(r + 8) * AS_STR + kc];
                a[mt][2] = As_[r * AS_STR + kc + 4];
                a[mt][3] = As_[(r + 8) * AS_STR + kc + 4];
            }
            #pragma unroll
            for (int nt = 0; nt < 4; nt++) {
                int c = wn + nt * 8 + (lane >> 2);
                bh[nt][0] = BH_[kc * BS_STR + c];
                bh[nt][1] = BH_[(kc + 4) * BS_STR + c];
                bl[nt][0] = BL_[kc * BS_STR + c];
                bl[nt][1] = BL_[(kc + 4) * BS_STR + c];
            }
            #pragma unroll
            for (int mt = 0; mt < 4; mt++)
                #pragma unroll
                for (int nt = 0; nt < 4; nt++) {
                    asm volatile(
                        "mma.sync.aligned.m16n8k16.row.col.f32.bf16.bf16.f32 "
                        "{%0,%1,%2,%3}, {%4,%5,%6,%7}, {%8,%9}, {%0,%1,%2,%3};"
                        : "+f"(acc[mt][nt][0]), "+f"(acc[mt][nt][1]),
                          "+f"(acc[mt][nt][2]), "+f"(acc[mt][nt][3])
                        : "r"(a[mt][0]), "r"(a[mt][1]), "r"(a[mt][2]), "r"(a[mt][3]),
                          "r"(bh[nt][0]), "r"(bh[nt][1]));
                    asm volatile(
                        "mma.sync.aligned.m16n8k16.row.col.f32.bf16.bf16.f32 "
                        "{%0,%1,%2,%3}, {%4,%5,%6,%7}, {%8,%9}, {%0,%1,%2,%3};"
                        : "+f"(acc[mt][nt][0]), "+f"(acc[mt][nt][1]),
                          "+f"(acc[mt][nt][2]), "+f"(acc[mt][nt][3])
                        : "r"(a[mt][0]), "r"(a[mt][1]), "r"(a[mt][2]), "r"(a[mt][3]),
                          "r"(bl[nt][0]), "r"(bl[nt][1]));
                }
        }
        __syncthreads();
    }

    // epilogue: bias + relu, packed bf16 stores
    #pragma unroll
    for (int mt = 0; mt < 4; mt++) {
        int rbase = m0 + wm + mt * 16 + (lane >> 2);
        #pragma unroll
        for (int nt = 0; nt < 4; nt++) {
            int c = n0 + wn + nt * 8 + (lane & 3) * 2;
            float bx = bias ? bias[c] : 0.f;
            float by = bias ? bias[c + 1] : 0.f;
            #pragma unroll
            for (int h = 0; h < 2; h++) {
                int r = rbase + h * 8;
                if (r >= M) continue;
                float v0 = acc[mt][nt][2 * h] + bx;
                float v1 = acc[mt][nt][2 * h + 1] + by;
                if (relu) { v0 = fmaxf(v0, 0.f); v1 = fmaxf(v1, 0.f); }
                *(unsigned*)(C + (size_t)r * N + c) = pack_bf2(v0, v1);
            }
        }
    }
    #undef CPA_TILE
}

// ---------------- MLP head (single block) ------------------------------------
__global__ void mlp_kernel(const float* __restrict__ Wf1, const float* __restrict__ bf1,
                           const float* __restrict__ Wf2, const float* __restrict__ bf2,
                           const float* __restrict__ Wf3, const float* __restrict__ bf3,
                           float* __restrict__ out, int M) {
    __shared__ float sg[256], s1[128], s2[64];
    int t = threadIdx.x;
    sg[t] = g_gsum[t] * (1.0f / (float)M);
    __syncthreads();
    if (t < 128) {
        float a = bf1[t];
        for (int k = 0; k < 256; k++) a += sg[k] * Wf1[k * 128 + t];
        s1[t] = fmaxf(a, 0.f);
    }
    __syncthreads();
    if (t < 64) {
        float a = bf2[t];
        for (int k = 0; k < 128; k++) a += s1[k] * Wf2[k * 64 + t];
        s2[t] = fmaxf(a, 0.f);
    }
    __syncthreads();
    if (t == 0) {
        float a = bf3[0];
        for (int k = 0; k < 64; k++) a += s2[k] * Wf3[k];
        out[0] = a;
    }
}

// ---------------- launcher ---------------------------------------------------
extern "C" void kernel_launch(void* const* d_in, const int* in_sizes, int n_in,
                              void* d_out, int out_size) {
    const float* x   = (const float*)d_in[0];
    const int*   ei  = (const int*)  d_in[1];
    const float* W1  = (const float*)d_in[2];  const float* b1  = (const float*)d_in[3];
    const float* W2  = (const float*)d_in[4];  const float* b2  = (const float*)d_in[5];
    const float* W3  = (const float*)d_in[6];  const float* b3  = (const float*)d_in[7];
    const float* Wf1 = (const float*)d_in[8];  const float* bf1 = (const float*)d_in[9];
    const float* Wf2 = (const float*)d_in[10]; const float* bf2 = (const float*)d_in[11];
    const float* Wf3 = (const float*)d_in[12]; const float* bf3 = (const float*)d_in[13];
    float* out = (float*)d_out;

    int M = in_sizes[0] / 128;   // 50000
    int E = in_sizes[1] / 2;     // 800000
    const int* row = ei;
    const int* col = ei + E;

    __nv_bfloat16 *bufA, *bufB;
    unsigned *wh1, *wl1, *wh2, *wl2, *wh3, *wl3;
    cudaGetSymbolAddress((void**)&bufA, g_bufA);
    cudaGetSymbolAddress((void**)&bufB, g_bufB);
    cudaGetSymbolAddress((void**)&wh1, g_wh1); cudaGetSymbolAddress((void**)&wl1, g_wl1);
    cudaGetSymbolAddress((void**)&wh2, g_wh2); cudaGetSymbolAddress((void**)&wl2, g_wl2);
    cudaGetSymbolAddress((void**)&wh3, g_wh3); cudaGetSymbolAddress((void**)&wl3, g_wl3);

    static int smem_set = 0;
    if (!smem_set) {
        cudaFuncSetAttribute(gemm_split, cudaFuncAttributeMaxDynamicSharedMemorySize,
                             GEMM_SMEM);
        smem_set = 1;
    }

    const int T = 256;
    int gN = (NN + T - 1) / T;
    int gE = (E + T - 1) / T;
    int gW = ((size_t)M * 32 + T - 1) / T;

    // --- graph setup + weight pre-split ---
    init_kernel<<<gN, T>>>();
    count_kernel<<<gE, T>>>(col, E);
    dinv_kernel<<<gN, T>>>(M);
    scanA_kernel<<<SCAN_B, 256>>>(M);
    scanB_kernel<<<1, 256>>>();
    scanC_kernel<<<SCAN_B, 256>>>(M);
    scatter_kernel<<<gE, T>>>(row, col, E);
    split_w_kernel<<<(64 * 256 + T - 1) / T, T>>>(W1, wh1, wl1, 64, 256);
    split_w_kernel<<<(128 * 512 + T - 1) / T, T>>>(W2, wh2, wl2, 128, 512);
    split_w_kernel<<<(256 * 256 + T - 1) / T, T>>>(W3, wh3, wl3, 256, 256);

    int gM = (M + 127) / 128;

    // --- layer 1: p1 = A_hat x ; h1 = relu(p1 @ W1 + b1) ---
    prop_f32_kernel<<<gW, T>>>(x, bufA, M);
    gemm_split<<<dim3(2, gM), 256, GEMM_SMEM>>>(bufA, wh1, wl1, b1, bufB, M, 256, 128, 1);

    // --- layer 2 ---
    prop_bf16_kernel<<<gW, T>>>(bufB, bufA, M);
    gemm_split<<<dim3(4, gM), 256, GEMM_SMEM>>>(bufA, wh2, wl2, b2, bufB, M, 512, 256, 1);

    // --- layer 3: t = h2 @ W3 ; fused prop + bias + relu + mean-pool ---
    gemm_split<<<dim3(2, gM), 256, GEMM_SMEM>>>(bufB, wh3, wl3, nullptr, bufA, M, 256, 512, 0);
    prop_pool_kernel<<<(M + 7) / 8, 256>>>(bufA, b3, M);

    // --- MLP head ---
    mlp_kernel<<<1, 256>>>(Wf1, bf1, Wf2, bf2, Wf3, bf3, out, M);
}

// round 15
// speedup vs baseline: 1.0054x; 1.0054x over previous
#include <cuda_runtime.h>
#include <cuda_bf16.h>
#include <cstdint>
#include <cstddef>

#define NN 50000
#define NE 800000
#define SCAN_CH 196          // ceil(50000/256)
#define SCAN_B  256

// ---------------- scratch (static __device__ arrays; no allocs allowed) ------
__device__ __align__(16) __nv_bfloat16 g_bufA[(size_t)NN * 256];  // 25.6 MB
__device__ __align__(16) __nv_bfloat16 g_bufB[(size_t)NN * 512];  // 51.2 MB
// pre-split weights: packed bf16x2 (k,k+1) hi/lo, layout [K/2][N] uints
__device__ __align__(16) unsigned g_wh1[64 * 256],  g_wl1[64 * 256];
__device__ __align__(16) unsigned g_wh2[128 * 512], g_wl2[128 * 512];
__device__ __align__(16) unsigned g_wh3[256 * 256], g_wl3[256 * 256];
__device__ float g_dinv[NN];
__device__ int   g_deg[NN];
__device__ int   g_off[NN];
__device__ int   g_cur[NN];
__device__ int   g_src[NE];
__device__ int   g_bsum[SCAN_B];
__device__ int   g_boff[SCAN_B];
__device__ float g_gsum[256];

// ---------------- setup kernels ---------------------------------------------
__global__ void init_kernel() {
    int i = blockIdx.x * blockDim.x + threadIdx.x;
    if (i < NN) { g_deg[i] = 0; g_cur[i] = 0; }
    if (i < 256) g_gsum[i] = 0.f;
}

__global__ void count_kernel(const int* __restrict__ col, int E) {
    int e = blockIdx.x * blockDim.x + threadIdx.x;
    if (e < E) atomicAdd(&g_deg[col[e]], 1);
}

__global__ void dinv_kernel(int n) {
    int i = blockIdx.x * blockDim.x + threadIdx.x;
    if (i < n) g_dinv[i] = rsqrtf((float)(g_deg[i] + 1));
}

__device__ __forceinline__ unsigned pack_bf2(float a, float b) {
    __nv_bfloat162 h = __floats2bfloat162_rn(a, b);
    return *(unsigned*)&h;
}

// split W[K,N] fp32 into packed hi/lo kpair uints [K/2][N]
__global__ void split_w_kernel(const float* __restrict__ W,
                               unsigned* __restrict__ Wh, unsigned* __restrict__ Wl,
                               int K2, int N) {
    int idx = blockIdx.x * blockDim.x + threadIdx.x;
    if (idx >= K2 * N) return;
    int kp = idx / N, c = idx - kp * N;
    float f0 = W[(size_t)(2 * kp) * N + c];
    float f1 = W[(size_t)(2 * kp + 1) * N + c];
    float h0 = __bfloat162float(__float2bfloat16(f0));
    float h1 = __bfloat162float(__float2bfloat16(f1));
    Wh[idx] = pack_bf2(h0, h1);
    Wl[idx] = pack_bf2(f0 - h0, f1 - h1);
}

// --- hierarchical exclusive scan of g_deg -> g_off ---------------------------
__global__ void scanA_kernel(int n) {
    __shared__ int ws[8];
    int t = threadIdx.x, lane = t & 31, wid = t >> 5;
    int i = blockIdx.x * SCAN_CH + t;
    int v = (t < SCAN_CH && i < n) ? g_deg[i] : 0;
    #pragma unroll
    for (int d = 16; d > 0; d >>= 1) v += __shfl_down_sync(0xffffffffu, v, d);
    if (lane == 0) ws[wid] = v;
    __syncthreads();
    if (t == 0) {
        int s = 0;
        #pragma unroll
        for (int w = 0; w < 8; w++) s += ws[w];
        g_bsum[blockIdx.x] = s;
    }
}

__global__ void scanB_kernel() {
    __shared__ int ws[8];
    int t = threadIdx.x, lane = t & 31, wid = t >> 5;
    int s = g_bsum[t];
    int v = s;
    #pragma unroll
    for (int d = 1; d < 32; d <<= 1) {
        int u = __shfl_up_sync(0xffffffffu, v, d);
        if (lane >= d) v += u;
    }
    if (lane == 31) ws[wid] = v;
    __syncthreads();
    if (wid == 0 && lane < 8) {
        int w = ws[lane];
        #pragma unroll
        for (int d = 1; d < 8; d <<= 1) {
            int u = __shfl_up_sync(0xffu, w, d);
            if (lane >= d) w += u;
        }
        ws[lane] = w;
    }
    __syncthreads();
    g_boff[t] = (v - s) + (wid ? ws[wid - 1] : 0);
}

__global__ void scanC_kernel(int n) {
    __shared__ int ws[8];
    int t = threadIdx.x, lane = t & 31, wid = t >> 5;
    int i = blockIdx.x * SCAN_CH + t;
    int s = (t < SCAN_CH && i < n) ? g_deg[i] : 0;
    int v = s;
    #pragma unroll
    for (int d = 1; d < 32; d <<= 1) {
        int u = __shfl_up_sync(0xffffffffu, v, d);
        if (lane >= d) v += u;
    }
    if (lane == 31) ws[wid] = v;
    __syncthreads();
    if (wid == 0 && lane < 8) {
        int w = ws[lane];
        #pragma unroll
        for (int d = 1; d < 8; d <<= 1) {
            int u = __shfl_up_sync(0xffu, w, d);
            if (lane >= d) w += u;
        }
        ws[lane] = w;
    }
    __syncthreads();
    if (t < SCAN_CH && i < n)
        g_off[i] = g_boff[blockIdx.x] + (v - s) + (wid ? ws[wid - 1] : 0);
}

__global__ void scatter_kernel(const int* __restrict__ row,
                               const int* __restrict__ col, int E) {
    int e = blockIdx.x * blockDim.x + threadIdx.x;
    if (e >= E) return;
    int c = col[e];
    int p = g_off[c] + atomicAdd(&g_cur[c], 1);
    g_src[p] = row[e];
}

// ---------------- propagation kernels (R4-proven) -----------------------------
__global__ void prop_f32_kernel(const float* __restrict__ in,
                                __nv_bfloat16* __restrict__ out, int n) {
    int warp = (blockIdx.x * blockDim.x + threadIdx.x) >> 5;
    int lane = threadIdx.x & 31;
    if (warp >= n) return;
    float dn = g_dinv[warp];
    float ws = dn * dn;
    float4 t = __ldg((const float4*)(in + (size_t)warp * 128 + lane * 4));
    float4 acc = make_float4(t.x * ws, t.y * ws, t.z * ws, t.w * ws);
    int s = g_off[warp];
    int e = s + g_deg[warp];
    for (int j = s; j < e; j++) {
        int r = __ldg(&g_src[j]);
        float wr = __ldg(&g_dinv[r]) * dn;
        float4 u = __ldg((const float4*)(in + (size_t)r * 128 + lane * 4));
        acc.x += u.x * wr; acc.y += u.y * wr; acc.z += u.z * wr; acc.w += u.w * wr;
    }
    __nv_bfloat162 o0 = __floats2bfloat162_rn(acc.x, acc.y);
    __nv_bfloat162 o1 = __floats2bfloat162_rn(acc.z, acc.w);
    uint2 o; o.x = *(unsigned*)&o0; o.y = *(unsigned*)&o1;
    *(uint2*)(out + (size_t)warp * 128 + lane * 4) = o;
}

__global__ void prop_bf16_kernel(const __nv_bfloat16* __restrict__ in,
                                 __nv_bfloat16* __restrict__ out, int n) {
    int warp = (blockIdx.x * blockDim.x + threadIdx.x) >> 5;
    int lane = threadIdx.x & 31;
    if (warp >= n) return;
    float dn = g_dinv[warp];
    float ws = dn * dn;
    float acc[8];
    {
        uint4 u = __ldg((const uint4*)(in + (size_t)warp * 256 + lane * 8));
        float2 f0 = __bfloat1622float2(*(__nv_bfloat162*)&u.x);
        float2 f1 = __bfloat1622float2(*(__nv_bfloat162*)&u.y);
        float2 f2 = __bfloat1622float2(*(__nv_bfloat162*)&u.z);
        float2 f3 = __bfloat1622float2(*(__nv_bfloat162*)&u.w);
        acc[0] = f0.x * ws; acc[1] = f0.y * ws; acc[2] = f1.x * ws; acc[3] = f1.y * ws;
        acc[4] = f2.x * ws; acc[5] = f2.y * ws; acc[6] = f3.x * ws; acc[7] = f3.y * ws;
    }
    int s = g_off[warp];
    int e = s + g_deg[warp];
    for (int j = s; j < e; j++) {
        int r = __ldg(&g_src[j]);
        float wr = __ldg(&g_dinv[r]) * dn;
        uint4 u = __ldg((const uint4*)(in + (size_t)r * 256 + lane * 8));
        float2 f0 = __bfloat1622float2(*(__nv_bfloat162*)&u.x);
        float2 f1 = __bfloat1622float2(*(__nv_bfloat162*)&u.y);
        float2 f2 = __bfloat1622float2(*(__nv_bfloat162*)&u.z);
        float2 f3 = __bfloat1622float2(*(__nv_bfloat162*)&u.w);
        acc[0] += f0.x * wr; acc[1] += f0.y * wr; acc[2] += f1.x * wr; acc[3] += f1.y * wr;
        acc[4] += f2.x * wr; acc[5] += f2.y * wr; acc[6] += f3.x * wr; acc[7] += f3.y * wr;
    }
    __nv_bfloat162 o0 = __floats2bfloat162_rn(acc[0], acc[1]);
    __nv_bfloat162 o1 = __floats2bfloat162_rn(acc[2], acc[3]);
    __nv_bfloat162 o2 = __floats2bfloat162_rn(acc[4], acc[5]);
    __nv_bfloat162 o3 = __floats2bfloat162_rn(acc[6], acc[7]);
    uint4 o; o.x = *(unsigned*)&o0; o.y = *(unsigned*)&o1;
    o.z = *(unsigned*)&o2; o.w = *(unsigned*)&o3;
    *(uint4*)(out + (size_t)warp * 256 + lane * 8) = o;
}

// layer-3 prop + relu + bias + mean-pool fused; warp-per-node (full parallelism),
// per-block smem reduction -> one atomicAdd per dim per block.
__global__ void prop_pool_kernel(const __nv_bfloat16* __restrict__ in,
                                 const float* __restrict__ b3, int n) {
    __shared__ float red[8][256];
    int wid = threadIdx.x >> 5, lane = threadIdx.x & 31;
    int node = blockIdx.x * 8 + wid;
    float vals[8];
    if (node < n) {
        float dn = g_dinv[node];
        float ws = dn * dn;
        float acc[8];
        {
            uint4 u = __ldg((const uint4*)(in + (size_t)node * 256 + lane * 8));
            float2 f0 = __bfloat1622float2(*(__nv_bfloat162*)&u.x);
            float2 f1 = __bfloat1622float2(*(__nv_bfloat162*)&u.y);
            float2 f2 = __bfloat1622float2(*(__nv_bfloat162*)&u.z);
            float2 f3 = __bfloat1622float2(*(__nv_bfloat162*)&u.w);
            acc[0] = f0.x * ws; acc[1] = f0.y * ws; acc[2] = f1.x * ws; acc[3] = f1.y * ws;
            acc[4] = f2.x * ws; acc[5] = f2.y * ws; acc[6] = f3.x * ws; acc[7] = f3.y * ws;
        }
        int s = g_off[node];
        int e = s + g_deg[node];
        for (int j = s; j < e; j++) {
            int r = __ldg(&g_src[j]);
            float wr = __ldg(&g_dinv[r]) * dn;
            uint4 u = __ldg((const uint4*)(in + (size_t)r * 256 + lane * 8));
            float2 f0 = __bfloat1622float2(*(__nv_bfloat162*)&u.x);
            float2 f1 = __bfloat1622float2(*(__nv_bfloat162*)&u.y);
            float2 f2 = __bfloat1622float2(*(__nv_bfloat162*)&u.z);
            float2 f3 = __bfloat1622float2(*(__nv_bfloat162*)&u.w);
            acc[0] += f0.x * wr; acc[1] += f0.y * wr; acc[2] += f1.x * wr; acc[3] += f1.y * wr;
            acc[4] += f2.x * wr; acc[5] += f2.y * wr; acc[6] += f3.x * wr; acc[7] += f3.y * wr;
        }
        #pragma unroll
        for (int q = 0; q < 8; q++)
            vals[q] = fmaxf(acc[q] + b3[lane * 8 + q], 0.f);
    } else {
        #pragma unroll
        for (int q = 0; q < 8; q++) vals[q] = 0.f;
    }
    #pragma unroll
    for (int q = 0; q < 8; q++) red[wid][lane * 8 + q] = vals[q];
    __syncthreads();
    int t = threadIdx.x;
    float s = 0.f;
    #pragma unroll
    for (int w = 0; w < 8; w++) s += red[w][t];
    atomicAdd(&g_gsum[t], s);
}

// ---------------- split-precision bf16 GEMM, cp.async double-buffered --------
// (R13-proven, byte-identical)
#define AS_STR 20    // uints/row (16 used)
#define BS_STR 136   // uints/kpair-row (128 used)
#define AS_TILE (128 * AS_STR)   // 2560 uints
#define BS_TILE (16 * BS_STR)    // 2176 uints
#define GEMM_SMEM (2 * (AS_TILE + 2 * BS_TILE) * 4)   // 55296 B

#define CP16(dst_u32, src) \
    asm volatile("cp.async.cg.shared.global [%0], [%1], 16;" :: "r"(dst_u32), "l"(src))

__global__ __launch_bounds__(256, 2)
void gemm_split(const __nv_bfloat16* __restrict__ A, const unsigned* __restrict__ Wh,
                const unsigned* __restrict__ Wl, const float* __restrict__ bias,
                __nv_bfloat16* __restrict__ C, int M, int N, int K, int relu) {
    extern __shared__ unsigned smem[];
    unsigned* AsBase = smem;                          // 2 x AS_TILE
    unsigned* BHBase = smem + 2 * AS_TILE;            // 2 x BS_TILE
    unsigned* BLBase = smem + 2 * AS_TILE + 2 * BS_TILE;  // 2 x BS_TILE
    const unsigned sb = (unsigned)__cvta_generic_to_shared(smem);
    const unsigned sbH = sb + 2 * AS_TILE * 4;
    const unsigned sbL = sb + (2 * AS_TILE + 2 * BS_TILE) * 4;

    const int tid = threadIdx.x, lane = tid & 31, wid = tid >> 5;
    const int m0 = blockIdx.y * 128, n0 = blockIdx.x * 128;
    const int wm = (wid >> 2) * 64;
    const int wn = (wid & 3) * 32;

    const int a_r0 = tid >> 2;             // 0..63
    const int a_r1 = a_r0 + 64;            // 64..127
    const int a_q = (tid & 3) * 4;         // uint offset 0,4,8,12
    const int a_rc0 = min(m0 + a_r0, M - 1);
    const int a_rc1 = min(m0 + a_r1, M - 1);
    const int b_kp0 = tid >> 5;            // 0..7
    const int b_kp1 = b_kp0 + 8;           // 8..15
    const int b_g = (tid & 31) * 4;        // col 0..124

    float acc[4][4][4];
    #pragma unroll
    for (int i = 0; i < 4; i++)
        #pragma unroll
        for (int j = 0; j < 4; j++)
            #pragma unroll
            for (int q = 0; q < 4; q++) acc[i][j][q] = 0.f;

    #define CPA_TILE(kt_, buf_) do {                                            \
        int k0_ = (kt_) << 5;                                                   \
        unsigned adst = sb + ((buf_) * AS_TILE) * 4;                            \
        CP16(adst + (a_r0 * AS_STR + a_q) * 4,                                  \
             A + (size_t)a_rc0 * K + k0_ + a_q * 2);                            \
        CP16(adst + (a_r1 * AS_STR + a_q) * 4,                                  \
             A + (size_t)a_rc1 * K + k0_ + a_q * 2);                            \
        int kb_ = k0_ >> 1;                                                     \
        unsigned hdst = sbH + ((buf_) * BS_TILE) * 4;                           \
        unsigned ldst = sbL + ((buf_) * BS_TILE) * 4;                           \
        CP16(hdst + (b_kp0 * BS_STR + b_g) * 4,                                 \
             Wh + (size_t)(kb_ + b_kp0) * N + n0 + b_g);                        \
        CP16(hdst + (b_kp1 * BS_STR + b_g) * 4,                                 \
             Wh + (size_t)(kb_ + b_kp1) * N + n0 + b_g);                        \
        CP16(ldst + (b_kp0 * BS_STR + b_g) * 4,                                 \
             Wl + (size_t)(kb_ + b_kp0) * N + n0 + b_g);                        \
        CP16(ldst + (b_kp1 * BS_STR + b_g) * 4,                                 \
             Wl + (size_t)(kb_ + b_kp1) * N + n0 + b_g);                        \
        asm volatile("cp.async.commit_group;");                                 \
    } while (0)

    const int KT = K >> 5;
    CPA_TILE(0, 0);
    for (int kt = 0; kt < KT; kt++) {
        const int cur = kt & 1;
        if (kt + 1 < KT) {
            CPA_TILE(kt + 1, cur ^ 1);
            asm volatile("cp.async.wait_group 1;");
        } else {
            asm volatile("cp.async.wait_group 0;");
        }
        __syncthreads();

        const unsigned* As_ = AsBase + cur * AS_TILE;
        const unsigned* BH_ = BHBase + cur * BS_TILE;
        const unsigned* BL_ = BLBase + cur * BS_TILE;
        #pragma unroll
        for (int ks = 0; ks < 2; ks++) {
            unsigned a[4][4], bh[4][2], bl[4][2];
            int kc = ks * 8 + (lane & 3);
            #pragma unroll
            for (int mt = 0; mt < 4; mt++) {
                int r = wm + mt * 16 + (lane >> 2);
                a[mt][0] = As_[r * AS_STR + kc];
                a[mt][1] = As_[(r + 8) * AS_STR + kc];
                a[mt][2] = As_[r * AS_STR + kc + 4];
                a[mt][3] = As_[(r + 8) * AS_STR + kc + 4];
            }
            #pragma unroll
            for (int nt = 0; nt < 4; nt++) {
                int c = wn + nt * 8 + (lane >> 2);
                bh[nt][0] = BH_[kc * BS_STR + c];
                bh[nt][1] = BH_[(kc + 4) * BS_STR + c];
                bl[nt][0] = BL_[kc * BS_STR + c];
                bl[nt][1] = BL_[(kc + 4) * BS_STR + c];
            }
            #pragma unroll
            for (int mt = 0; mt < 4; mt++)
                #pragma unroll
                for (int nt = 0; nt < 4; nt++) {
                    asm volatile(
                        "mma.sync.aligned.m16n8k16.row.col.f32.bf16.bf16.f32 "
                        "{%0,%1,%2,%3}, {%4,%5,%6,%7}, {%8,%9}, {%0,%1,%2,%3};"
                        : "+f"(acc[mt][nt][0]), "+f"(acc[mt][nt][1]),
                          "+f"(acc[mt][nt][2]), "+f"(acc[mt][nt][3])
                        : "r"(a[mt][0]), "r"(a[mt][1]), "r"(a[mt][2]), "r"(a[mt][3]),
                          "r"(bh[nt][0]), "r"(bh[nt][1]));
                    asm volatile(
                        "mma.sync.aligned.m16n8k16.row.col.f32.bf16.bf16.f32 "
                        "{%0,%1,%2,%3}, {%4,%5,%6,%7}, {%8,%9}, {%0,%1,%2,%3};"
                        : "+f"(acc[mt][nt][0]), "+f"(acc[mt][nt][1]),
                          "+f"(acc[mt][nt][2]), "+f"(acc[mt][nt][3])
                        : "r"(a[mt][0]), "r"(a[mt][1]), "r"(a[mt][2]), "r"(a[mt][3]),
                          "r"(bl[nt][0]), "r"(bl[nt][1]));
                }
        }
        __syncthreads();
    }

    // epilogue: bias + relu, packed bf16 stores
    #pragma unroll
    for (int mt = 0; mt < 4; mt++) {
        int rbase = m0 + wm + mt * 16 + (lane >> 2);
        #pragma unroll
        for (int nt = 0; nt < 4; nt++) {
            int c = n0 + wn + nt * 8 + (lane & 3) * 2;
            float bx = bias ? bias[c] : 0.f;
            float by = bias ? bias[c + 1] : 0.f;
            #pragma unroll
            for (int h = 0; h < 2; h++) {
                int r = rbase + h * 8;
                if (r >= M) continue;
                float v0 = acc[mt][nt][2 * h] + bx;
                float v1 = acc[mt][nt][2 * h + 1] + by;
                if (relu) { v0 = fmaxf(v0, 0.f); v1 = fmaxf(v1, 0.f); }
                *(unsigned*)(C + (size_t)r * N + c) = pack_bf2(v0, v1);
            }
        }
    }
    #undef CPA_TILE
}

// ---------------- MLP head (single block) ------------------------------------
__global__ void mlp_kernel(const float* __restrict__ Wf1, const float* __restrict__ bf1,
                           const float* __restrict__ Wf2, const float* __restrict__ bf2,
                           const float* __restrict__ Wf3, const float* __restrict__ bf3,
                           float* __restrict__ out, int M) {
    __shared__ float sg[256], s1[128], s2[64];
    int t = threadIdx.x;
    sg[t] = g_gsum[t] * (1.0f / (float)M);
    __syncthreads();
    if (t < 128) {
        float a = bf1[t];
        for (int k = 0; k < 256; k++) a += sg[k] * Wf1[k * 128 + t];
        s1[t] = fmaxf(a, 0.f);
    }
    __syncthreads();
    if (t < 64) {
        float a = bf2[t];
        for (int k = 0; k < 128; k++) a += s1[k] * Wf2[k * 64 + t];
        s2[t] = fmaxf(a, 0.f);
    }
    __syncthreads();
    if (t == 0) {
        float a = bf3[0];
        for (int k = 0; k < 64; k++) a += s2[k] * Wf3[k];
        out[0] = a;
    }
}

// ---------------- launcher ---------------------------------------------------
extern "C" void kernel_launch(void* const* d_in, const int* in_sizes, int n_in,
                              void* d_out, int out_size) {
    const float* x   = (const float*)d_in[0];
    const int*   ei  = (const int*)  d_in[1];
    const float* W1  = (const float*)d_in[2];  const float* b1  = (const float*)d_in[3];
    const float* W2  = (const float*)d_in[4];  const float* b2  = (const float*)d_in[5];
    const float* W3  = (const float*)d_in[6];  const float* b3  = (const float*)d_in[7];
    const float* Wf1 = (const float*)d_in[8];  const float* bf1 = (const float*)d_in[9];
    const float* Wf2 = (const float*)d_in[10]; const float* bf2 = (const float*)d_in[11];
    const float* Wf3 = (const float*)d_in[12]; const float* bf3 = (const float*)d_in[13];
    float* out = (float*)d_out;

    int M = in_sizes[0] / 128;   // 50000
    int E = in_sizes[1] / 2;     // 800000
    const int* row = ei;
    const int* col = ei + E;

    __nv_bfloat16 *bufA, *bufB;
    unsigned *wh1, *wl1, *wh2, *wl2, *wh3, *wl3;
    cudaGetSymbolAddress((void**)&bufA, g_bufA);
    cudaGetSymbolAddress((void**)&bufB, g_bufB);
    cudaGetSymbolAddress((void**)&wh1, g_wh1); cudaGetSymbolAddress((void**)&wl1, g_wl1);
    cudaGetSymbolAddress((void**)&wh2, g_wh2); cudaGetSymbolAddress((void**)&wl2, g_wl2);
    cudaGetSymbolAddress((void**)&wh3, g_wh3); cudaGetSymbolAddress((void**)&wl3, g_wl3);

    static int smem_set = 0;
    if (!smem_set) {
        cudaFuncSetAttribute(gemm_split, cudaFuncAttributeMaxDynamicSharedMemorySize,
                             GEMM_SMEM);
        smem_set = 1;
    }

    const int T = 256;
    int gN = (NN + T - 1) / T;
    int gE = (E + T - 1) / T;
    int gW = ((size_t)M * 32 + T - 1) / T;

    // --- graph setup + weight pre-split ---
    init_kernel<<<gN, T>>>();
    count_kernel<<<gE, T>>>(col, E);
    dinv_kernel<<<gN, T>>>(M);
    scanA_kernel<<<SCAN_B, 256>>>(M);
    scanB_kernel<<<1, 256>>>();
    scanC_kernel<<<SCAN_B, 256>>>(M);
    scatter_kernel<<<gE, T>>>(row, col, E);
    split_w_kernel<<<(64 * 256 + T - 1) / T, T>>>(W1, wh1, wl1, 64, 256);
    split_w_kernel<<<(128 * 512 + T - 1) / T, T>>>(W2, wh2, wl2, 128, 512);
    split_w_kernel<<<(256 * 256 + T - 1) / T, T>>>(W3, wh3, wl3, 256, 256);

    int gM = (M + 127) / 128;

    // --- layer 1: p1 = A_hat x ; h1 = relu(p1 @ W1 + b1) ---
    prop_f32_kernel<<<gW, T>>>(x, bufA, M);
    gemm_split<<<dim3(2, gM), 256, GEMM_SMEM>>>(bufA, wh1, wl1, b1, bufB, M, 256, 128, 1);

    // --- layer 2 ---
    prop_bf16_kernel<<<gW, T>>>(bufB, bufA, M);
    gemm_split<<<dim3(4, gM), 256, GEMM_SMEM>>>(bufA, wh2, wl2, b2, bufB, M, 512, 256, 1);

    // --- layer 3: t = h2 @ W3 ; fused prop + bias + relu + mean-pool ---
    gemm_split<<<dim3(2, gM), 256, GEMM_SMEM>>>(bufB, wh3, wl3, nullptr, bufA, M, 256, 512, 0);
    prop_pool_kernel<<<(M + 7) / 8, 256>>>(bufA, b3, M);

    // --- MLP head ---
    mlp_kernel<<<1, 256>>>(Wf1, bf1, Wf2, bf2, Wf3, bf3, out, M);
}

// round 16
// speedup vs baseline: 1.0871x; 1.0813x over previous
#include <cuda_runtime.h>
#include <cuda_bf16.h>
#include <cstdint>
#include <cstddef>

#define NN 50000
#define NE 800000
#define SCAN_CH 196          // ceil(50000/256)
#define SCAN_B  256

// ---------------- scratch (static __device__ arrays; no allocs allowed) ------
__device__ __align__(16) __nv_bfloat16 g_bufA[(size_t)NN * 256];  // 25.6 MB
__device__ __align__(16) __nv_bfloat16 g_bufB[(size_t)NN * 512];  // 51.2 MB
// pre-split weights: packed bf16x2 (k,k+1) hi/lo, layout [K/2][N] uints
__device__ __align__(16) unsigned g_wh1[64 * 256],  g_wl1[64 * 256];
__device__ __align__(16) unsigned g_wh2[128 * 512], g_wl2[128 * 512];
__device__ __align__(16) unsigned g_wh3[256 * 256], g_wl3[256 * 256];
__device__ float g_dinv[NN];
__device__ int   g_deg[NN];
__device__ int   g_off[NN];
__device__ int   g_cur[NN];
__device__ int   g_src[NE];
__device__ int   g_bsum[SCAN_B];
__device__ float g_gsum[256];

// ---------------- setup kernels ---------------------------------------------
__global__ void init_kernel() {
    int i = blockIdx.x * blockDim.x + threadIdx.x;
    if (i < NN) g_deg[i] = 0;
    if (i < 256) g_gsum[i] = 0.f;
}

__global__ void count_kernel(const int* __restrict__ col, int E) {
    int e = blockIdx.x * blockDim.x + threadIdx.x;
    if (e < E) atomicAdd(&g_deg[col[e]], 1);
}

__device__ __forceinline__ unsigned pack_bf2(float a, float b) {
    __nv_bfloat162 h = __floats2bfloat162_rn(a, b);
    return *(unsigned*)&h;
}

// scanA: per-block partial sums of g_deg + fused dinv computation
__global__ void scanA_kernel(int n) {
    __shared__ int ws[8];
    int t = threadIdx.x, lane = t & 31, wid = t >> 5;
    int i = blockIdx.x * SCAN_CH + t;
    int d = (t < SCAN_CH && i < n) ? g_deg[i] : 0;
    if (t < SCAN_CH && i < n) g_dinv[i] = rsqrtf((float)(d + 1));  // fused
    int v = d;
    #pragma unroll
    for (int dd = 16; dd > 0; dd >>= 1) v += __shfl_down_sync(0xffffffffu, v, dd);
    if (lane == 0) ws[wid] = v;
    __syncthreads();
    if (t == 0) {
        int s = 0;
        #pragma unroll
        for (int w = 0; w < 8; w++) s += ws[w];
        g_bsum[blockIdx.x] = s;
    }
}

// scanC: per-block local scan; block offset computed in-kernel from g_bsum
// (redundant 256-scan per block replaces the separate scanB launch).
// Also zeroes g_cur.
__global__ void scanC_kernel(int n) {
    __shared__ int pre[SCAN_B];
    __shared__ int ws[8];
    int t = threadIdx.x, lane = t & 31, wid = t >> 5;

    // inclusive scan of g_bsum into pre[]
    {
        int s = g_bsum[t];
        int v = s;
        #pragma unroll
        for (int d = 1; d < 32; d <<= 1) {
            int u = __shfl_up_sync(0xffffffffu, v, d);
            if (lane >= d) v += u;
        }
        if (lane == 31) ws[wid] = v;
        __syncthreads();
        if (wid == 0 && lane < 8) {
            int w = ws[lane];
            #pragma unroll
            for (int d = 1; d < 8; d <<= 1) {
                int u = __shfl_up_sync(0xffu, w, d);
                if (lane >= d) w += u;
            }
            ws[lane] = w;
        }
        __syncthreads();
        pre[t] = v + (wid ? ws[wid - 1] : 0);
        __syncthreads();
    }
    int boff = (blockIdx.x > 0) ? pre[blockIdx.x - 1] : 0;
    __syncthreads();

    // local exclusive scan of this block's chunk
    int i = blockIdx.x * SCAN_CH + t;
    int s = (t < SCAN_CH && i < n) ? g_deg[i] : 0;
    int v = s;
    #pragma unroll
    for (int d = 1; d < 32; d <<= 1) {
        int u = __shfl_up_sync(0xffffffffu, v, d);
        if (lane >= d) v += u;
    }
    if (lane == 31) ws[wid] = v;
    __syncthreads();
    if (wid == 0 && lane < 8) {
        int w = ws[lane];
        #pragma unroll
        for (int d = 1; d < 8; d <<= 1) {
            int u = __shfl_up_sync(0xffu, w, d);
            if (lane >= d) w += u;
        }
        ws[lane] = w;
    }
    __syncthreads();
    if (t < SCAN_CH && i < n) {
        g_off[i] = boff + (v - s) + (wid ? ws[wid - 1] : 0);
        g_cur[i] = 0;                      // fused cursor init
    }
}

__global__ void scatter_kernel(const int* __restrict__ row,
                               const int* __restrict__ col, int E) {
    int e = blockIdx.x * blockDim.x + threadIdx.x;
    if (e >= E) return;
    int c = col[e];
    int p = g_off[c] + atomicAdd(&g_cur[c], 1);
    g_src[p] = row[e];
}

// one kernel splitting all three weight matrices into packed hi/lo arrays
#define SW1 (64 * 256)
#define SW2 (128 * 512)
#define SW3 (256 * 256)
__global__ void split_w_all(const float* __restrict__ W1, const float* __restrict__ W2,
                            const float* __restrict__ W3,
                            unsigned* __restrict__ wh1, unsigned* __restrict__ wl1,
                            unsigned* __restrict__ wh2, unsigned* __restrict__ wl2,
                            unsigned* __restrict__ wh3, unsigned* __restrict__ wl3) {
    int idx = blockIdx.x * blockDim.x + threadIdx.x;
    const float* W; unsigned *Wh, *Wl; int N, li;
    if (idx < SW1)              { W = W1; Wh = wh1; Wl = wl1; N = 256; li = idx; }
    else if (idx < SW1 + SW2)   { W = W2; Wh = wh2; Wl = wl2; N = 512; li = idx - SW1; }
    else if (idx < SW1 + SW2 + SW3) { W = W3; Wh = wh3; Wl = wl3; N = 256; li = idx - SW1 - SW2; }
    else return;
    int kp = li / N, c = li - kp * N;
    float f0 = W[(size_t)(2 * kp) * N + c];
    float f1 = W[(size_t)(2 * kp + 1) * N + c];
    float h0 = __bfloat162float(__float2bfloat16(f0));
    float h1 = __bfloat162float(__float2bfloat16(f1));
    Wh[li] = pack_bf2(h0, h1);
    Wl[li] = pack_bf2(f0 - h0, f1 - h1);
}

// ---------------- propagation kernels (R4-proven) -----------------------------
__global__ void prop_f32_kernel(const float* __restrict__ in,
                                __nv_bfloat16* __restrict__ out, int n) {
    int warp = (blockIdx.x * blockDim.x + threadIdx.x) >> 5;
    int lane = threadIdx.x & 31;
    if (warp >= n) return;
    float dn = g_dinv[warp];
    float ws = dn * dn;
    float4 t = __ldg((const float4*)(in + (size_t)warp * 128 + lane * 4));
    float4 acc = make_float4(t.x * ws, t.y * ws, t.z * ws, t.w * ws);
    int s = g_off[warp];
    int e = s + g_deg[warp];
    for (int j = s; j < e; j++) {
        int r = __ldg(&g_src[j]);
        float wr = __ldg(&g_dinv[r]) * dn;
        float4 u = __ldg((const float4*)(in + (size_t)r * 128 + lane * 4));
        acc.x += u.x * wr; acc.y += u.y * wr; acc.z += u.z * wr; acc.w += u.w * wr;
    }
    __nv_bfloat162 o0 = __floats2bfloat162_rn(acc.x, acc.y);
    __nv_bfloat162 o1 = __floats2bfloat162_rn(acc.z, acc.w);
    uint2 o; o.x = *(unsigned*)&o0; o.y = *(unsigned*)&o1;
    *(uint2*)(out + (size_t)warp * 128 + lane * 4) = o;
}

__global__ void prop_bf16_kernel(const __nv_bfloat16* __restrict__ in,
                                 __nv_bfloat16* __restrict__ out, int n) {
    int warp = (blockIdx.x * blockDim.x + threadIdx.x) >> 5;
    int lane = threadIdx.x & 31;
    if (warp >= n) return;
    float dn = g_dinv[warp];
    float ws = dn * dn;
    float acc[8];
    {
        uint4 u = __ldg((const uint4*)(in + (size_t)warp * 256 + lane * 8));
        float2 f0 = __bfloat1622float2(*(__nv_bfloat162*)&u.x);
        float2 f1 = __bfloat1622float2(*(__nv_bfloat162*)&u.y);
        float2 f2 = __bfloat1622float2(*(__nv_bfloat162*)&u.z);
        float2 f3 = __bfloat1622float2(*(__nv_bfloat162*)&u.w);
        acc[0] = f0.x * ws; acc[1] = f0.y * ws; acc[2] = f1.x * ws; acc[3] = f1.y * ws;
        acc[4] = f2.x * ws; acc[5] = f2.y * ws; acc[6] = f3.x * ws; acc[7] = f3.y * ws;
    }
    int s = g_off[warp];
    int e = s + g_deg[warp];
    for (int j = s; j < e; j++) {
        int r = __ldg(&g_src[j]);
        float wr = __ldg(&g_dinv[r]) * dn;
        uint4 u = __ldg((const uint4*)(in + (size_t)r * 256 + lane * 8));
        float2 f0 = __bfloat1622float2(*(__nv_bfloat162*)&u.x);
        float2 f1 = __bfloat1622float2(*(__nv_bfloat162*)&u.y);
        float2 f2 = __bfloat1622float2(*(__nv_bfloat162*)&u.z);
        float2 f3 = __bfloat1622float2(*(__nv_bfloat162*)&u.w);
        acc[0] += f0.x * wr; acc[1] += f0.y * wr; acc[2] += f1.x * wr; acc[3] += f1.y * wr;
        acc[4] += f2.x * wr; acc[5] += f2.y * wr; acc[6] += f3.x * wr; acc[7] += f3.y * wr;
    }
    __nv_bfloat162 o0 = __floats2bfloat162_rn(acc[0], acc[1]);
    __nv_bfloat162 o1 = __floats2bfloat162_rn(acc[2], acc[3]);
    __nv_bfloat162 o2 = __floats2bfloat162_rn(acc[4], acc[5]);
    __nv_bfloat162 o3 = __floats2bfloat162_rn(acc[6], acc[7]);
    uint4 o; o.x = *(unsigned*)&o0; o.y = *(unsigned*)&o1;
    o.z = *(unsigned*)&o2; o.w = *(unsigned*)&o3;
    *(uint4*)(out + (size_t)warp * 256 + lane * 8) = o;
}

// ---------------- split-precision bf16 GEMM, cp.async double-buffered --------
// (R13-proven, byte-identical)
#define AS_STR 20    // uints/row (16 used)
#define BS_STR 136   // uints/kpair-row (128 used)
#define AS_TILE (128 * AS_STR)   // 2560 uints
#define BS_TILE (16 * BS_STR)    // 2176 uints
#define GEMM_SMEM (2 * (AS_TILE + 2 * BS_TILE) * 4)   // 55296 B

#define CP16(dst_u32, src) \
    asm volatile("cp.async.cg.shared.global [%0], [%1], 16;" :: "r"(dst_u32), "l"(src))

__global__ __launch_bounds__(256, 2)
void gemm_split(const __nv_bfloat16* __restrict__ A, const unsigned* __restrict__ Wh,
                const unsigned* __restrict__ Wl, const float* __restrict__ bias,
                __nv_bfloat16* __restrict__ C, int M, int N, int K, int relu) {
    extern __shared__ unsigned smem[];
    unsigned* AsBase = smem;                          // 2 x AS_TILE
    unsigned* BHBase = smem + 2 * AS_TILE;            // 2 x BS_TILE
    unsigned* BLBase = smem + 2 * AS_TILE + 2 * BS_TILE;  // 2 x BS_TILE
    const unsigned sb = (unsigned)__cvta_generic_to_shared(smem);
    const unsigned sbH = sb + 2 * AS_TILE * 4;
    const unsigned sbL = sb + (2 * AS_TILE + 2 * BS_TILE) * 4;

    const int tid = threadIdx.x, lane = tid & 31, wid = tid >> 5;
    const int m0 = blockIdx.y * 128, n0 = blockIdx.x * 128;
    const int wm = (wid >> 2) * 64;
    const int wn = (wid & 3) * 32;

    const int a_r0 = tid >> 2;             // 0..63
    const int a_r1 = a_r0 + 64;            // 64..127
    const int a_q = (tid & 3) * 4;         // uint offset 0,4,8,12
    const int a_rc0 = min(m0 + a_r0, M - 1);
    const int a_rc1 = min(m0 + a_r1, M - 1);
    const int b_kp0 = tid >> 5;            // 0..7
    const int b_kp1 = b_kp0 + 8;           // 8..15
    const int b_g = (tid & 31) * 4;        // col 0..124

    float acc[4][4][4];
    #pragma unroll
    for (int i = 0; i < 4; i++)
        #pragma unroll
        for (int j = 0; j < 4; j++)
            #pragma unroll
            for (int q = 0; q < 4; q++) acc[i][j][q] = 0.f;

    #define CPA_TILE(kt_, buf_) do {                                            \
        int k0_ = (kt_) << 5;                                                   \
        unsigned adst = sb + ((buf_) * AS_TILE) * 4;                            \
        CP16(adst + (a_r0 * AS_STR + a_q) * 4,                                  \
             A + (size_t)a_rc0 * K + k0_ + a_q * 2);                            \
        CP16(adst + (a_r1 * AS_STR + a_q) * 4,                                  \
             A + (size_t)a_rc1 * K + k0_ + a_q * 2);                            \
        int kb_ = k0_ >> 1;                                                     \
        unsigned hdst = sbH + ((buf_) * BS_TILE) * 4;                           \
        unsigned ldst = sbL + ((buf_) * BS_TILE) * 4;                           \
        CP16(hdst + (b_kp0 * BS_STR + b_g) * 4,                                 \
             Wh + (size_t)(kb_ + b_kp0) * N + n0 + b_g);                        \
        CP16(hdst + (b_kp1 * BS_STR + b_g) * 4,                                 \
             Wh + (size_t)(kb_ + b_kp1) * N + n0 + b_g);                        \
        CP16(ldst + (b_kp0 * BS_STR + b_g) * 4,                                 \
             Wl + (size_t)(kb_ + b_kp0) * N + n0 + b_g);                        \
        CP16(ldst + (b_kp1 * BS_STR + b_g) * 4,                                 \
             Wl + (size_t)(kb_ + b_kp1) * N + n0 + b_g);                        \
        asm volatile("cp.async.commit_group;");                                 \
    } while (0)

    const int KT = K >> 5;
    CPA_TILE(0, 0);
    for (int kt = 0; kt < KT; kt++) {
        const int cur = kt & 1;
        if (kt + 1 < KT) {
            CPA_TILE(kt + 1, cur ^ 1);
            asm volatile("cp.async.wait_group 1;");
        } else {
            asm volatile("cp.async.wait_group 0;");
        }
        __syncthreads();

        const unsigned* As_ = AsBase + cur * AS_TILE;
        const unsigned* BH_ = BHBase + cur * BS_TILE;
        const unsigned* BL_ = BLBase + cur * BS_TILE;
        #pragma unroll
        for (int ks = 0; ks < 2; ks++) {
            unsigned a[4][4], bh[4][2], bl[4][2];
            int kc = ks * 8 + (lane & 3);
            #pragma unroll
            for (int mt = 0; mt < 4; mt++) {
                int r = wm + mt * 16 + (lane >> 2);
                a[mt][0] = As_[r * AS_STR + kc];
                a[mt][1] = As_[(r + 8) * AS_STR + kc];
                a[mt][2] = As_[r * AS_STR + kc + 4];
                a[mt][3] = As_[(r + 8) * AS_STR + kc + 4];
            }
            #pragma unroll
            for (int nt = 0; nt < 4; nt++) {
                int c = wn + nt * 8 + (lane >> 2);
                bh[nt][0] = BH_[kc * BS_STR + c];
                bh[nt][1] = BH_[(kc + 4) * BS_STR + c];
                bl[nt][0] = BL_[kc * BS_STR + c];
                bl[nt][1] = BL_[(kc + 4) * BS_STR + c];
            }
            #pragma unroll
            for (int mt = 0; mt < 4; mt++)
                #pragma unroll
                for (int nt = 0; nt < 4; nt++) {
                    asm volatile(
                        "mma.sync.aligned.m16n8k16.row.col.f32.bf16.bf16.f32 "
                        "{%0,%1,%2,%3}, {%4,%5,%6,%7}, {%8,%9}, {%0,%1,%2,%3};"
                        : "+f"(acc[mt][nt][0]), "+f"(acc[mt][nt][1]),
                          "+f"(acc[mt][nt][2]), "+f"(acc[mt][nt][3])
                        : "r"(a[mt][0]), "r"(a[mt][1]), "r"(a[mt][2]), "r"(a[mt][3]),
                          "r"(bh[nt][0]), "r"(bh[nt][1]));
                    asm volatile(
                        "mma.sync.aligned.m16n8k16.row.col.f32.bf16.bf16.f32 "
                        "{%0,%1,%2,%3}, {%4,%5,%6,%7}, {%8,%9}, {%0,%1,%2,%3};"
                        : "+f"(acc[mt][nt][0]), "+f"(acc[mt][nt][1]),
                          "+f"(acc[mt][nt][2]), "+f"(acc[mt][nt][3])
                        : "r"(a[mt][0]), "r"(a[mt][1]), "r"(a[mt][2]), "r"(a[mt][3]),
                          "r"(bl[nt][0]), "r"(bl[nt][1]));
                }
        }
        __syncthreads();
    }

    // epilogue: bias + relu, packed bf16 stores
    #pragma unroll
    for (int mt = 0; mt < 4; mt++) {
        int rbase = m0 + wm + mt * 16 + (lane >> 2);
        #pragma unroll
        for (int nt = 0; nt < 4; nt++) {
            int c = n0 + wn + nt * 8 + (lane & 3) * 2;
            float bx = bias ? bias[c] : 0.f;
            float by = bias ? bias[c + 1] : 0.f;
            #pragma unroll
            for (int h = 0; h < 2; h++) {
                int r = rbase + h * 8;
                if (r >= M) continue;
                float v0 = acc[mt][nt][2 * h] + bx;
                float v1 = acc[mt][nt][2 * h + 1] + by;
                if (relu) { v0 = fmaxf(v0, 0.f); v1 = fmaxf(v1, 0.f); }
                *(unsigned*)(C + (size_t)r * N + c) = pack_bf2(v0, v1);
            }
        }
    }
    #undef CPA_TILE
}

// ---------------- pool: column sums of relu(in + b3) -------------------------
__global__ void pool_kernel(const __nv_bfloat16* __restrict__ in,
                            const float* __restrict__ b3, int M) {
    int d = threadIdx.x;
    int per = (M + gridDim.x - 1) / gridDim.x;
    int n0 = blockIdx.x * per;
    int n1 = min(M, n0 + per);
    float bias = b3[d];
    float acc = 0.f;
    for (int n = n0; n < n1; n++)
        acc += fmaxf(__bfloat162float(in[(size_t)n * 256 + d]) + bias, 0.f);
    atomicAdd(&g_gsum[d], acc);
}

// ---------------- MLP head (single block) ------------------------------------
__global__ void mlp_kernel(const float* __restrict__ Wf1, const float* __restrict__ bf1,
                           const float* __restrict__ Wf2, const float* __restrict__ bf2,
                           const float* __restrict__ Wf3, const float* __restrict__ bf3,
                           float* __restrict__ out, int M) {
    __shared__ float sg[256], s1[128], s2[64];
    int t = threadIdx.x;
    sg[t] = g_gsum[t] * (1.0f / (float)M);
    __syncthreads();
    if (t < 128) {
        float a = bf1[t];
        for (int k = 0; k < 256; k++) a += sg[k] * Wf1[k * 128 + t];
        s1[t] = fmaxf(a, 0.f);
    }
    __syncthreads();
    if (t < 64) {
        float a = bf2[t];
        for (int k = 0; k < 128; k++) a += s1[k] * Wf2[k * 64 + t];
        s2[t] = fmaxf(a, 0.f);
    }
    __syncthreads();
    if (t == 0) {
        float a = bf3[0];
        for (int k = 0; k < 64; k++) a += s2[k] * Wf3[k];
        out[0] = a;
    }
}

// ---------------- launcher ---------------------------------------------------
extern "C" void kernel_launch(void* const* d_in, const int* in_sizes, int n_in,
                              void* d_out, int out_size) {
    const float* x   = (const float*)d_in[0];
    const int*   ei  = (const int*)  d_in[1];
    const float* W1  = (const float*)d_in[2];  const float* b1  = (const float*)d_in[3];
    const float* W2  = (const float*)d_in[4];  const float* b2  = (const float*)d_in[5];
    const float* W3  = (const float*)d_in[6];  const float* b3  = (const float*)d_in[7];
    const float* Wf1 = (const float*)d_in[8];  const float* bf1 = (const float*)d_in[9];
    const float* Wf2 = (const float*)d_in[10]; const float* bf2 = (const float*)d_in[11];
    const float* Wf3 = (const float*)d_in[12]; const float* bf3 = (const float*)d_in[13];
    float* out = (float*)d_out;

    int M = in_sizes[0] / 128;   // 50000
    int E = in_sizes[1] / 2;     // 800000
    const int* row = ei;
    const int* col = ei + E;

    __nv_bfloat16 *bufA, *bufB;
    unsigned *wh1, *wl1, *wh2, *wl2, *wh3, *wl3;
    cudaGetSymbolAddress((void**)&bufA, g_bufA);
    cudaGetSymbolAddress((void**)&bufB, g_bufB);
    cudaGetSymbolAddress((void**)&wh1, g_wh1); cudaGetSymbolAddress((void**)&wl1, g_wl1);
    cudaGetSymbolAddress((void**)&wh2, g_wh2); cudaGetSymbolAddress((void**)&wl2, g_wl2);
    cudaGetSymbolAddress((void**)&wh3, g_wh3); cudaGetSymbolAddress((void**)&wl3, g_wl3);

    static int smem_set = 0;
    if (!smem_set) {
        cudaFuncSetAttribute(gemm_split, cudaFuncAttributeMaxDynamicSharedMemorySize,
                             GEMM_SMEM);
        smem_set = 1;
    }

    const int T = 256;
    int gN = (NN + T - 1) / T;
    int gE = (E + T - 1) / T;
    int gW = ((size_t)M * 32 + T - 1) / T;

    // --- compacted graph setup + weight pre-split (6 launches) ---
    init_kernel<<<gN, T>>>();
    count_kernel<<<gE, T>>>(col, E);
    scanA_kernel<<<SCAN_B, 256>>>(M);                 // partial sums + dinv
    scanC_kernel<<<SCAN_B, 256>>>(M);                 // offsets + cursor init
    scatter_kernel<<<gE, T>>>(row, col, E);
    split_w_all<<<(SW1 + SW2 + SW3 + T - 1) / T, T>>>(W1, W2, W3,
                                                      wh1, wl1, wh2, wl2, wh3, wl3);

    int gM = (M + 127) / 128;

    // --- layer 1: p1 = A_hat x ; h1 = relu(p1 @ W1 + b1) ---
    prop_f32_kernel<<<gW, T>>>(x, bufA, M);
    gemm_split<<<dim3(2, gM), 256, GEMM_SMEM>>>(bufA, wh1, wl1, b1, bufB, M, 256, 128, 1);

    // --- layer 2 ---
    prop_bf16_kernel<<<gW, T>>>(bufB, bufA, M);
    gemm_split<<<dim3(4, gM), 256, GEMM_SMEM>>>(bufA, wh2, wl2, b2, bufB, M, 512, 256, 1);

    // --- layer 3: t = h2 @ W3 ; p3 = A_hat t ---
    gemm_split<<<dim3(2, gM), 256, GEMM_SMEM>>>(bufB, wh3, wl3, nullptr, bufA, M, 256, 512, 0);
    prop_bf16_kernel<<<gW, T>>>(bufA, bufB, M);

    // --- mean pool + MLP head ---
    pool_kernel<<<200, 256>>>(bufB, b3, M);
    mlp_kernel<<<1, 256>>>(Wf1, bf1, Wf2, bf2, Wf3, bf3, out, M);
}